// round 3
// baseline (speedup 1.0000x reference)
#include <cuda_runtime.h>

#define NEG_INF (-1e8f)
#define INVLN2 1.4426950408889634f
#define LN2    0.6931471805599453f

__device__ __forceinline__ float ex2f(float x){ float r; asm("ex2.approx.ftz.f32 %0, %1;" : "=f"(r) : "f"(x)); return r; }
__device__ __forceinline__ float lg2f(float x){ float r; asm("lg2.approx.ftz.f32 %0, %1;" : "=f"(r) : "f"(x)); return r; }

// logsumexp in log2 domain: 2 MUFU ops
__device__ __forceinline__ float lse2(float a, float b){
    float m = fmaxf(a, b);
    float d = fabsf(a - b);
    return m + lg2f(1.0f + ex2f(-d));
}
// 3-term, 4 MUFU ops
__device__ __forceinline__ float lse3(float a, float b, float c){
    float m = fmaxf(fmaxf(a, b), c);
    return m + lg2f(ex2f(a - m) + ex2f(b - m) + ex2f(c - m));
}
// named barrier over one 128-thread group (4 contiguous warps)
__device__ __forceinline__ void gbar(int id){
    asm volatile("bar.sync %0, %1;" :: "r"(id), "r"(128) : "memory");
}

// CTA = 2 independent groups of 128 threads; group g handles batch 2*blockIdx.x+g.
// Thread t of a group owns grid columns 2t, 2t+1 (even/odd).
// All math in log2 domain (inputs scaled by 1/ln2 at load; output scaled back).
// Row recurrence per column j:
//   u0 = th0 + LSE3(Vdiag + A[0,:]), u1 = th1 + LSE3(Vup + A[1,:])
//   x_j = LSE(c_j, a_j + x_{j-1}),  c_j = th2 + LSE2(u0_{j-1}+A[2,0], u1_{j-1}+A[2,1]),
//   a_j = th2 + A[2,2]   -- scanned via associative pair composition.
__global__ __launch_bounds__(256, 1)
void forward_decoder_kernel(const float* __restrict__ theta,
                            const float* __restrict__ A,
                            float* __restrict__ out){
    constexpr int N = 256, M = 256;
    const int tid  = threadIdx.x;
    const int g    = tid >> 7;      // group 0/1
    const int t    = tid & 127;     // column-pair index
    const int lane = tid & 31;
    const int wg   = t >> 5;        // warp within group (0..3)
    const int b    = blockIdx.x * 2 + g;

    __shared__ float sU0[2][128], sU1[2][128];
    __shared__ float sAA[2][4],  sAC[2][4];

    const float* thb = theta + (size_t)b * N * M * 3;
    const float* Ab  = A     + (size_t)b * N * M * 9;

    // prefetch row 0: 3 + 9 float2 loads, 8B-aligned, warp covers 3KB contiguous
    float2 p[12];
    {
        const float2* tp = (const float2*)(thb + 6 * (size_t)t);
        const float2* ap = (const float2*)(Ab + 18 * (size_t)t);
        p[0]=__ldg(tp); p[1]=__ldg(tp+1); p[2]=__ldg(tp+2);
        #pragma unroll
        for(int k = 0; k < 9; k++) p[3+k] = __ldg(ap + k);
    }

    // previous-row V for own even/odd columns
    float pv0e=NEG_INF, pv1e=NEG_INF, pv2e=NEG_INF;
    float pv0o=NEG_INF, pv1o=NEG_INF, pv2o=NEG_INF;
    // previous-row V at column 2t-1 (neighbor's odd column / own Cexc)
    float dn0=NEG_INF, dn1=NEG_INF, dn2=NEG_INF;

    for(int i = 0; i < N; i++){
        // consume prefetched row (scale into log2 domain)
        float t0e=p[0].x*INVLN2, t1e=p[0].y*INVLN2, t2e=p[1].x*INVLN2;
        float t0o=p[1].y*INVLN2, t1o=p[2].x*INVLN2, t2o=p[2].y*INVLN2;
        float e0=p[3].x*INVLN2, e1=p[3].y*INVLN2, e2=p[4].x*INVLN2;
        float e3=p[4].y*INVLN2, e4=p[5].x*INVLN2, e5=p[5].y*INVLN2;
        float e6=p[6].x*INVLN2, e7=p[6].y*INVLN2, e8=p[7].x*INVLN2;
        float o0=p[7].y*INVLN2, o1=p[8].x*INVLN2, o2=p[8].y*INVLN2;
        float o3=p[9].x*INVLN2, o4=p[9].y*INVLN2, o5=p[10].x*INVLN2;
        float o6=p[10].y*INVLN2, o7=p[11].x*INVLN2, o8=p[11].y*INVLN2;

        // issue next row's loads immediately (overlap HBM with the row's compute)
        if(i + 1 < N){
            const float2* tp = (const float2*)(thb + (size_t)(i+1)*768  + 6  * (size_t)t);
            const float2* ap = (const float2*)(Ab  + (size_t)(i+1)*2304 + 18 * (size_t)t);
            p[0]=__ldg(tp); p[1]=__ldg(tp+1); p[2]=__ldg(tp+2);
            #pragma unroll
            for(int k = 0; k < 9; k++) p[3+k] = __ldg(ap + k);
        }

        // diagonal source for even column = prev-row V at col 2t-1
        float d0, d1, d2;
        if(t == 0){ float bv = (i == 0) ? 0.0f : NEG_INF; d0=bv; d1=bv; d2=bv; }
        else      { d0=dn0; d1=dn1; d2=dn2; }

        float u0e  = t0e + lse3(d0  + e0, d1  + e1, d2  + e2);
        float u1e  = t1e + lse3(pv0e + e3, pv1e + e4, pv2e + e5);
        float nu0o = t0o + lse3(pv0e + o0, pv1e + o1, pv2e + o2);  // odd diag = own even prev V
        float nu1o = t1o + lse3(pv0o + o3, pv1o + o4, pv2o + o5);

        // exchange this row's odd-column u with right neighbor
        sU0[g][t] = nu0o; sU1[g][t] = nu1o;
        gbar(1 + g);                              // barrier A
        float num0 = (t == 0) ? NEG_INF : sU0[g][t-1];
        float num1 = (t == 0) ? NEG_INF : sU1[g][t-1];

        float c_e = t2e + lse2(num0 + e6, num1 + e7);  // u at col 2t-1 (this row)
        float c_o = t2o + lse2(u0e  + o6, u1e  + o7);  // u at col 2t   (this row)
        float a_e = t2e + e8;
        float a_o = t2o + o8;

        // compose (even then odd) into one scan element per thread
        float iA = a_e + a_o;
        float iC = lse2(c_o, a_o + c_e);

        // inclusive Kogge-Stone over 32 lanes
        #pragma unroll
        for(int dlt = 1; dlt < 32; dlt <<= 1){
            float aI = __shfl_up_sync(0xffffffffu, iA, dlt);
            float cI = __shfl_up_sync(0xffffffffu, iC, dlt);
            if(lane >= dlt){ iC = lse2(iC, iA + cI); iA += aI; }
        }
        if(lane == 31){ sAA[g][wg] = iA; sAC[g][wg] = iC; }
        gbar(1 + g);                              // barrier B

        // cross-warp exclusive prefix over 4 warp aggregates (redundant per warp)
        float pC = NEG_INF;
        {
            float wa = (lane < 4) ? sAA[g][lane] : 0.0f;
            float wc = (lane < 4) ? sAC[g][lane] : NEG_INF;
            #pragma unroll
            for(int dlt = 1; dlt < 4; dlt <<= 1){
                float aI = __shfl_up_sync(0xffffffffu, wa, dlt);
                float cI = __shfl_up_sync(0xffffffffu, wc, dlt);
                if(lane >= dlt && lane < 4){ wc = lse2(wc, wa + cI); wa += aI; }
            }
            if(wg > 0) pC = __shfl_sync(0xffffffffu, wc, wg - 1);
        }

        // exclusive-within-warp, then fold in warp prefix
        float eA = __shfl_up_sync(0xffffffffu, iA, 1);
        float eC = __shfl_up_sync(0xffffffffu, iC, 1);
        if(lane == 0){ eA = 0.0f; eC = NEG_INF; }
        float Cexc = (wg > 0) ? lse2(eC, eA + pC) : eC;   // = x at column 2t-1

        float x_e = lse2(c_e, a_e + Cexc);
        float x_o = (wg > 0) ? lse2(iC, iA + pC) : iC;    // inclusive through col 2t+1

        // roll state for next row (no 3rd barrier: Cexc IS next row's diag V2;
        // num0/num1 ARE next row's diag u0/u1 at col 2t-1)
        pv0e = u0e;  pv1e = u1e;  pv2e = x_e;
        pv0o = nu0o; pv1o = nu1o; pv2o = x_o;
        dn0  = num0; dn1  = num1; dn2  = Cexc;
    }

    // terminal: logsumexp over states at last row, last grid column (odd col of t=127)
    if(t == 127) out[b] = LN2 * lse3(pv0o, pv1o, pv2o);
}

extern "C" void kernel_launch(void* const* d_in, const int* in_sizes, int n_in,
                              void* d_out, int out_size) {
    const float* theta = (const float*)d_in[0];
    const float* A     = (const float*)d_in[1];
    // d_in[2] = pos: fixed [(-1,-1),(-1,0),(0,-1)] -> (diag, up, left), hard-coded.
    float* out = (float*)d_out;
    int B = out_size;                 // 128
    forward_decoder_kernel<<<B / 2, 256>>>(theta, A, out);
}